// round 16
// baseline (speedup 1.0000x reference)
#include <cuda_runtime.h>

typedef unsigned long long u64;

// ---- hardware tanh (single MUFU op on sm_100) ----
__device__ __forceinline__ float tnha(float x) {
    float r; asm("tanh.approx.f32 %0, %1;" : "=f"(r) : "f"(x)); return r;
}
// ---- packed f32x2 helpers ----
__device__ __forceinline__ u64 f2fma(u64 a, u64 b, u64 c) {
    u64 d; asm("fma.rn.f32x2 %0, %1, %2, %3;" : "=l"(d) : "l"(a), "l"(b), "l"(c)); return d;
}
__device__ __forceinline__ u64 f2pack(float lo, float hi) {
    u64 d; asm("mov.b64 %0, {%1, %2};" : "=l"(d) : "f"(lo), "f"(hi)); return d;
}
__device__ __forceinline__ void f2unpack(u64 v, float &lo, float &hi) {
    asm("mov.b64 {%0, %1}, %2;" : "=f"(lo), "=f"(hi) : "l"(v));
}

#define NW 4    // warps per block
#define NP 4    // element-PAIRS per thread (8 elements/thread, 16/warp)
#define NB 8    // batches per block
#define ROW 20  // floats per m-row of sHp (padded: 16B-aligned, bank-spread)

// Each thread owns hidden unit u (lane&15) for 4 packed element pairs.
// Gates accumulate as f32x2; weights come from smem as duplicated pairs.
// Sigmoid gates (i,f,o) use 0.5x-prescaled weights: sig = 0.5*tanh(a_half)+0.5.
__global__ void __launch_bounds__(128, 4) infect_lstm_kernel(
    const float* __restrict__ mob,   // [B,7]
    const float* __restrict__ ctrl,  // [B,5]
    const float* __restrict__ Wcc,   // [3,5]
    const float* __restrict__ bcc,   // [3]
    const float* __restrict__ Wih,   // [64,1]
    const float* __restrict__ Whh,   // [64,16]
    const float* __restrict__ bih,   // [64]
    const float* __restrict__ bhh,   // [64]
    const float* __restrict__ W1,    // [16,19]
    const float* __restrict__ b1,    // [16]
    const float* __restrict__ W2,    // [16,16]
    const float* __restrict__ b2,    // [16]
    const float* __restrict__ W3,    // [1,16]
    const float* __restrict__ b3,    // [1]
    float* __restrict__ out)         // [B]
{
    __shared__ __align__(16) u64 sWif[16 * 16 * 2]; // [(m*16+u)*2] -> (.5wi,.5wi),(.5wf,.5wf)
    __shared__ __align__(16) u64 sWgo[16 * 16 * 2]; // -> (wg,wg),(.5wo,.5wo)
    __shared__ __align__(16) u64 sW1d[19 * 16];     // dup-packed W1T [i][u]
    __shared__ __align__(16) u64 sW2d[16 * 16];     // dup-packed W2T [i][u]
    __shared__ __align__(16) u64 sWccd[15];         // dup-packed Wcc
    __shared__ float sW3[16], sB1[16], sB2[16], sBcc[3], sB3[1];
    // h exchange: [slot][warp][m*ROW + 2*pg], pg = 4*g+p, value = (h_e0, h_e1)
    __shared__ __align__(16) float sHp[2][NW][16 * ROW];

    const int tid = threadIdx.x;
    const int lane = tid & 31;
    const int u = lane & 15;
    const int g = lane >> 4;
    const int w = tid >> 5;

    // ---- smem weight fill (dup-packed) ----
    for (int i = tid; i < 256; i += 128) {
        int m = i >> 4, uu = i & 15;
        float wi = 0.5f * Whh[(0 * 16 + uu) * 16 + m];
        float wf = 0.5f * Whh[(16 + uu) * 16 + m];
        float wg = Whh[(32 + uu) * 16 + m];
        float wo = 0.5f * Whh[(48 + uu) * 16 + m];
        sWif[i * 2]     = f2pack(wi, wi);
        sWif[i * 2 + 1] = f2pack(wf, wf);
        sWgo[i * 2]     = f2pack(wg, wg);
        sWgo[i * 2 + 1] = f2pack(wo, wo);
        float w2v = W2[uu * 16 + m];
        sW2d[i] = f2pack(w2v, w2v);
    }
    for (int i = tid; i < 19 * 16; i += 128) {
        int col = i >> 4, uu = i & 15;
        float v = W1[uu * 19 + col];
        sW1d[i] = f2pack(v, v);
    }
    if (tid < 16) { sW3[tid] = W3[tid]; sB1[tid] = b1[tid]; sB2[tid] = b2[tid]; }
    else if (tid < 31) { float v = Wcc[tid - 16]; sWccd[tid - 16] = f2pack(v, v); }
    else if (tid < 34) sBcc[tid - 31] = bcc[tid - 31];
    else if (tid == 34) sB3[0] = b3[0];
    __syncthreads();

    // ---- per-u constants (packed; sigmoid rows prescaled by 0.5) ----
    const u64 wxi2 = f2pack(0.5f * Wih[u],      0.5f * Wih[u]);
    const u64 wxf2 = f2pack(0.5f * Wih[16 + u], 0.5f * Wih[16 + u]);
    const u64 wxg2 = f2pack(Wih[32 + u],        Wih[32 + u]);
    const u64 wxo2 = f2pack(0.5f * Wih[48 + u], 0.5f * Wih[48 + u]);
    const float bi = 0.5f * (bih[u] + bhh[u]);
    const float bf = 0.5f * (bih[16 + u] + bhh[16 + u]);
    const float bg = bih[32 + u] + bhh[32 + u];
    const float bo = 0.5f * (bih[48 + u] + bhh[48 + u]);
    const u64 bi2 = f2pack(bi, bi), bf2 = f2pack(bf, bf);
    const u64 bg2 = f2pack(bg, bg), bo2 = f2pack(bo, bo);

    // ---- batch loop ----
#pragma unroll 1
    for (int bi_ = 0; bi_ < NB; bi_++) {
        const int ebase = ((blockIdx.x * NB + bi_) * NW + w) * 16;  // 16 elems/warp
        const float* mpg = mob + (size_t)(ebase + 8 * g) * 7;       // local elem k at +7k

        __syncwarp();   // prior batch's slot-0 reads complete before reuse
        float cc[2 * NP];
#pragma unroll
        for (int p = 0; p < NP; p++) {
            cc[2 * p] = 0.0f; cc[2 * p + 1] = 0.0f;
            *(float2*)&sHp[0][w][u * ROW + 8 * g + 2 * p] = make_float2(0.0f, 0.0f);
        }
        __syncwarp();

        // ---- LSTM: 7 steps ----
#pragma unroll
        for (int s = 0; s < 7; s++) {
            const float* hr = &sHp[s & 1][w][0];
            float* hwp = &sHp[(s & 1) ^ 1][w][0];
            u64 ai[NP], af_[NP], ag[NP], ao[NP];
#pragma unroll
            for (int p = 0; p < NP; p++) {
                u64 xp = f2pack(mpg[14 * p + s], mpg[14 * p + 7 + s]);
                ai[p]  = f2fma(xp, wxi2, bi2);
                af_[p] = f2fma(xp, wxf2, bf2);
                ag[p]  = f2fma(xp, wxg2, bg2);
                ao[p]  = f2fma(xp, wxo2, bo2);
            }
#pragma unroll
            for (int m = 0; m < 16; m++) {
                ulonglong2 wif = *(const ulonglong2*)&sWif[(m * 16 + u) * 2];
                ulonglong2 wgo = *(const ulonglong2*)&sWgo[(m * 16 + u) * 2];
                ulonglong2 hq0 = *(const ulonglong2*)&hr[m * ROW + 8 * g];      // pairs 0,1
                ulonglong2 hq1 = *(const ulonglong2*)&hr[m * ROW + 8 * g + 4];  // pairs 2,3
                ai[0]  = f2fma(hq0.x, wif.x, ai[0]);  af_[0] = f2fma(hq0.x, wif.y, af_[0]);
                ag[0]  = f2fma(hq0.x, wgo.x, ag[0]);  ao[0]  = f2fma(hq0.x, wgo.y, ao[0]);
                ai[1]  = f2fma(hq0.y, wif.x, ai[1]);  af_[1] = f2fma(hq0.y, wif.y, af_[1]);
                ag[1]  = f2fma(hq0.y, wgo.x, ag[1]);  ao[1]  = f2fma(hq0.y, wgo.y, ao[1]);
                ai[2]  = f2fma(hq1.x, wif.x, ai[2]);  af_[2] = f2fma(hq1.x, wif.y, af_[2]);
                ag[2]  = f2fma(hq1.x, wgo.x, ag[2]);  ao[2]  = f2fma(hq1.x, wgo.y, ao[2]);
                ai[3]  = f2fma(hq1.y, wif.x, ai[3]);  af_[3] = f2fma(hq1.y, wif.y, af_[3]);
                ag[3]  = f2fma(hq1.y, wgo.x, ag[3]);  ao[3]  = f2fma(hq1.y, wgo.y, ao[3]);
            }
#pragma unroll
            for (int p = 0; p < NP; p++) {
                float a0, a1v, i0, i1, f0, f1, g0, g1, o0, o1;
                f2unpack(ai[p],  a0, a1v); i0 = fmaf(0.5f, tnha(a0), 0.5f); i1 = fmaf(0.5f, tnha(a1v), 0.5f);
                f2unpack(af_[p], a0, a1v); f0 = fmaf(0.5f, tnha(a0), 0.5f); f1 = fmaf(0.5f, tnha(a1v), 0.5f);
                f2unpack(ag[p],  a0, a1v); g0 = tnha(a0); g1 = tnha(a1v);
                f2unpack(ao[p],  a0, a1v); o0 = fmaf(0.5f, tnha(a0), 0.5f); o1 = fmaf(0.5f, tnha(a1v), 0.5f);
                cc[2 * p]     = fmaf(f0, cc[2 * p],     i0 * g0);
                cc[2 * p + 1] = fmaf(f1, cc[2 * p + 1], i1 * g1);
                float h0 = o0 * tnha(cc[2 * p]);
                float h1 = o1 * tnha(cc[2 * p + 1]);
                *(float2*)&hwp[u * ROW + 8 * g + 2 * p] = make_float2(h0, h1);
            }
            __syncwarp();
        }
        // final h in slot 1

        // ---- control head (packed) ----
        const float* cpg = ctrl + (size_t)(ebase + 8 * g) * 5;
        u64 ctl0[NP], ctl1[NP], ctl2[NP];
        {
            u64 bc0 = f2pack(sBcc[0], sBcc[0]);
            u64 bc1 = f2pack(sBcc[1], sBcc[1]);
            u64 bc2 = f2pack(sBcc[2], sBcc[2]);
#pragma unroll
            for (int p = 0; p < NP; p++) { ctl0[p] = bc0; ctl1[p] = bc1; ctl2[p] = bc2; }
        }
#pragma unroll
        for (int i = 0; i < 5; i++) {
            u64 wa = sWccd[i], wb = sWccd[5 + i], wc = sWccd[10 + i];
#pragma unroll
            for (int p = 0; p < NP; p++) {
                u64 v = f2pack(cpg[10 * p + i], cpg[10 * p + 5 + i]);
                ctl0[p] = f2fma(v, wa, ctl0[p]);
                ctl1[p] = f2fma(v, wb, ctl1[p]);
                ctl2[p] = f2fma(v, wc, ctl2[p]);
            }
        }

        // ---- FC1: 19->16, tanh (packed) ----
        u64 a1p[NP];
        {
            u64 b1d = f2pack(sB1[u], sB1[u]);
#pragma unroll
            for (int p = 0; p < NP; p++) a1p[p] = b1d;
        }
        const float* h1r = &sHp[1][w][0];
#pragma unroll
        for (int m = 0; m < 16; m++) {
            u64 w1 = sW1d[m * 16 + u];
            ulonglong2 hq0 = *(const ulonglong2*)&h1r[m * ROW + 8 * g];
            ulonglong2 hq1 = *(const ulonglong2*)&h1r[m * ROW + 8 * g + 4];
            a1p[0] = f2fma(hq0.x, w1, a1p[0]);
            a1p[1] = f2fma(hq0.y, w1, a1p[1]);
            a1p[2] = f2fma(hq1.x, w1, a1p[2]);
            a1p[3] = f2fma(hq1.y, w1, a1p[3]);
        }
        {
            u64 wc0 = sW1d[16 * 16 + u], wc1 = sW1d[17 * 16 + u], wc2 = sW1d[18 * 16 + u];
#pragma unroll
            for (int p = 0; p < NP; p++) {
                a1p[p] = f2fma(ctl0[p], wc0, a1p[p]);
                a1p[p] = f2fma(ctl1[p], wc1, a1p[p]);
                a1p[p] = f2fma(ctl2[p], wc2, a1p[p]);
            }
        }
        // tanh, exchange via slot 0 (last slot-0 read was step s=6; its end-of-step
        // __syncwarp covers the WAR hazard)
#pragma unroll
        for (int p = 0; p < NP; p++) {
            float a0, a1v;
            f2unpack(a1p[p], a0, a1v);
            *(float2*)&sHp[0][w][u * ROW + 8 * g + 2 * p] = make_float2(tnha(a0), tnha(a1v));
        }
        __syncwarp();

        // ---- FC2: 16->16, tanh (packed) ----
        u64 a2p[NP];
        {
            u64 b2d = f2pack(sB2[u], sB2[u]);
#pragma unroll
            for (int p = 0; p < NP; p++) a2p[p] = b2d;
        }
        const float* x1r = &sHp[0][w][0];
#pragma unroll
        for (int m = 0; m < 16; m++) {
            u64 w2 = sW2d[m * 16 + u];
            ulonglong2 hq0 = *(const ulonglong2*)&x1r[m * ROW + 8 * g];
            ulonglong2 hq1 = *(const ulonglong2*)&x1r[m * ROW + 8 * g + 4];
            a2p[0] = f2fma(hq0.x, w2, a2p[0]);
            a2p[1] = f2fma(hq0.y, w2, a2p[1]);
            a2p[2] = f2fma(hq1.x, w2, a2p[2]);
            a2p[3] = f2fma(hq1.y, w2, a2p[3]);
        }

        // ---- FC3: 16->1, relu; scalar butterfly per element ----
        float w3v = sW3[u];
        float bout = sB3[0];
#pragma unroll
        for (int p = 0; p < NP; p++) {
            float a0, a1v;
            f2unpack(a2p[p], a0, a1v);
            float p0 = tnha(a0) * w3v;
            float p1 = tnha(a1v) * w3v;
#pragma unroll
            for (int off = 8; off; off >>= 1) {
                p0 += __shfl_xor_sync(0xffffffffu, p0, off, 16);
                p1 += __shfl_xor_sync(0xffffffffu, p1, off, 16);
            }
            if (u == 0) {
                out[ebase + 8 * g + 2 * p]     = fmaxf(p0 + bout, 0.0f);
                out[ebase + 8 * g + 2 * p + 1] = fmaxf(p1 + bout, 0.0f);
            }
        }
    }
}

extern "C" void kernel_launch(void* const* d_in, const int* in_sizes, int n_in,
                              void* d_out, int out_size)
{
    const float* mob  = (const float*)d_in[0];
    const float* ctrl = (const float*)d_in[1];
    const float* Wcc  = (const float*)d_in[3];
    const float* bcc  = (const float*)d_in[4];
    const float* Wih  = (const float*)d_in[5];
    const float* Whh  = (const float*)d_in[6];
    const float* bih  = (const float*)d_in[7];
    const float* bhh  = (const float*)d_in[8];
    const float* W1   = (const float*)d_in[9];
    const float* b1   = (const float*)d_in[10];
    const float* W2   = (const float*)d_in[11];
    const float* b2   = (const float*)d_in[12];
    const float* W3   = (const float*)d_in[13];
    const float* b3   = (const float*)d_in[14];

    int B = in_sizes[2];
    int per_block = 16 * NW * NB;                  // 512 elements per block
    int blocks = (B + per_block - 1) / per_block;  // 2048 for B=1M

    infect_lstm_kernel<<<blocks, 128>>>(mob, ctrl, Wcc, bcc, Wih, Whh, bih, bhh,
                                        W1, b1, W2, b2, W3, b3, (float*)d_out);
}

// round 17
// speedup vs baseline: 1.0195x; 1.0195x over previous
#include <cuda_runtime.h>

// ---- hardware tanh (single MUFU op on sm_100) ----
__device__ __forceinline__ float tnha(float x) {
    float r; asm("tanh.approx.f32 %0, %1;" : "=f"(r) : "f"(x)); return r;
}
// sigmoid(x) = 0.5*tanh(x/2) + 0.5
__device__ __forceinline__ float siga(float x) {
    return fmaf(0.5f, tnha(0.5f * x), 0.5f);
}

#define NW 4   // warps per block
#define EPT 4  // elements per thread
#define NB 8   // batches per block (prologue amortization)
// Block = 128 threads = 4 warps; each warp handles 8 elements per batch,
// NB batches sequentially. Weights in smem/registers loaded once per block.
// Step body is ELEMENT-SEQUENTIAL: element k's activations overlap element
// k+1's m-loop (independent chains) to break the per-step FMA-pipe drain.
__global__ void __launch_bounds__(128, 4) infect_lstm_kernel(
    const float* __restrict__ mob,   // [B,7]
    const float* __restrict__ ctrl,  // [B,5]
    const float* __restrict__ Wcc,   // [3,5]
    const float* __restrict__ bcc,   // [3]
    const float* __restrict__ Wih,   // [64,1]
    const float* __restrict__ Whh,   // [64,16]
    const float* __restrict__ bih,   // [64]
    const float* __restrict__ bhh,   // [64]
    const float* __restrict__ W1,    // [16,19]
    const float* __restrict__ b1,    // [16]
    const float* __restrict__ W2,    // [16,16]
    const float* __restrict__ b2,    // [16]
    const float* __restrict__ W3,    // [1,16]
    const float* __restrict__ b3,    // [1]
    float* __restrict__ out)         // [B]
{
    __shared__ __align__(16) float4 sWhhT[16 * 16]; // [m][u] -> (wi,wf,wg,wo)
    __shared__ __align__(16) float4 sWxB[16];       // [u] -> Wih per gate
    __shared__ __align__(16) float4 sBiasV[16];     // [u] -> bih+bhh per gate
    __shared__ float sW1T[19 * 16];                 // [i][u] = W1[u][i]
    __shared__ float sW2T[16 * 16];                 // [i][u] = W2[u][i]
    __shared__ float sW3[16], sB1[16], sB2[16];
    __shared__ float sWcc[15], sBcc[3], sB3[1];
    // h exchange: [slot][warp][elemLocal*16+u], 8 elements per warp, double-buffered
    __shared__ __align__(16) float sH[2][NW][128];

    const int tid = threadIdx.x;

    for (int i = tid; i < 256; i += 128) {
        int m = i >> 4, uu = i & 15;
        sWhhT[i] = make_float4(Whh[uu * 16 + m],
                               Whh[(16 + uu) * 16 + m],
                               Whh[(32 + uu) * 16 + m],
                               Whh[(48 + uu) * 16 + m]);
        sW2T[i] = W2[uu * 16 + m];   // [i=m][u]
    }
    for (int i = tid; i < 19 * 16; i += 128) {
        int col = i >> 4, uu = i & 15;
        sW1T[i] = W1[uu * 19 + col];
    }
    if (tid < 16) {
        int uu = tid;
        sWxB[uu]   = make_float4(Wih[uu], Wih[16 + uu], Wih[32 + uu], Wih[48 + uu]);
        sBiasV[uu] = make_float4(bih[uu]      + bhh[uu],
                                 bih[16 + uu] + bhh[16 + uu],
                                 bih[32 + uu] + bhh[32 + uu],
                                 bih[48 + uu] + bhh[48 + uu]);
        sW3[uu] = W3[uu]; sB1[uu] = b1[uu]; sB2[uu] = b2[uu];
    } else if (tid < 31) sWcc[tid - 16] = Wcc[tid - 16];
    else if (tid < 34) sBcc[tid - 31] = bcc[tid - 31];
    else if (tid == 34) sB3[0] = b3[0];
    __syncthreads();

    const int lane = tid & 31;
    const int u = lane & 15;
    const int g = lane >> 4;                 // lane group (0/1)
    const int w = tid >> 5;                  // warp id within block

    // ---- hoist this lane's Whh column set into registers (64 regs, shared) ----
    float4 wreg[16];
#pragma unroll
    for (int m = 0; m < 16; m++) wreg[m] = sWhhT[m * 16 + u];

    const float4 wx = sWxB[u];
    const float4 bb = sBiasV[u];

    // ---- batch loop: NB batches of 32 elements, weights stay resident ----
#pragma unroll 1
    for (int bi = 0; bi < NB; bi++) {
        const int ebase = ((blockIdx.x * NB + bi) * NW + w) * (2 * EPT);
        const float* mpg = mob  + (size_t)(ebase + g) * 7;   // element k at +14*k
        const float* cpg = ctrl + (size_t)(ebase + g) * 5;   // element k at +10*k

        __syncwarp();    // prior batch's sH[0] reads done before reuse
        float cc[EPT];
#pragma unroll
        for (int k = 0; k < EPT; k++) {
            cc[k] = 0.0f;
            sH[0][w][(2 * k + g) * 16 + u] = 0.0f;
        }
        __syncwarp();

        // ---- LSTM: 7 steps; element-sequential body ----
#pragma unroll
        for (int s = 0; s < 7; s++) {
            const int rp = s & 1, wp = rp ^ 1;
#pragma unroll
            for (int k = 0; k < EPT; k++) {
                float x = mpg[14 * k + s];
                float ai = fmaf(x, wx.x, bb.x);
                float af = fmaf(x, wx.y, bb.y);
                float ag = fmaf(x, wx.z, bb.z);
                float ao = fmaf(x, wx.w, bb.w);
#pragma unroll
                for (int m4 = 0; m4 < 4; m4++) {
                    float4 hv = *(const float4*)&sH[rp][w][(2 * k + g) * 16 + m4 * 4];
                    const float4 w0 = wreg[m4 * 4 + 0];
                    const float4 w1 = wreg[m4 * 4 + 1];
                    const float4 w2 = wreg[m4 * 4 + 2];
                    const float4 w3 = wreg[m4 * 4 + 3];
                    ai = fmaf(hv.x, w0.x, ai);
                    af = fmaf(hv.x, w0.y, af);
                    ag = fmaf(hv.x, w0.z, ag);
                    ao = fmaf(hv.x, w0.w, ao);
                    ai = fmaf(hv.y, w1.x, ai);
                    af = fmaf(hv.y, w1.y, af);
                    ag = fmaf(hv.y, w1.z, ag);
                    ao = fmaf(hv.y, w1.w, ao);
                    ai = fmaf(hv.z, w2.x, ai);
                    af = fmaf(hv.z, w2.y, af);
                    ag = fmaf(hv.z, w2.z, ag);
                    ao = fmaf(hv.z, w2.w, ao);
                    ai = fmaf(hv.w, w3.x, ai);
                    af = fmaf(hv.w, w3.y, af);
                    ag = fmaf(hv.w, w3.z, ag);
                    ao = fmaf(hv.w, w3.w, ao);
                }
                float ig = siga(ai);
                float fg = siga(af);
                float gg = tnha(ag);
                float og = siga(ao);
                cc[k] = fmaf(fg, cc[k], ig * gg);
                sH[wp][w][(2 * k + g) * 16 + u] = og * tnha(cc[k]);
            }
            __syncwarp();
        }
        // final h is in slot 1

        // ---- control heads ----
        float c0[EPT], c1[EPT], c2[EPT];
#pragma unroll
        for (int k = 0; k < EPT; k++) { c0[k] = sBcc[0]; c1[k] = sBcc[1]; c2[k] = sBcc[2]; }
#pragma unroll
        for (int i = 0; i < 5; i++) {
            float wa = sWcc[i], wb = sWcc[5 + i], wc = sWcc[10 + i];
#pragma unroll
            for (int k = 0; k < EPT; k++) {
                float v = cpg[10 * k + i];
                c0[k] = fmaf(v, wa, c0[k]);
                c1[k] = fmaf(v, wb, c1[k]);
                c2[k] = fmaf(v, wc, c2[k]);
            }
        }

        // ---- FC1: 19->16, tanh; element-sequential ----
        {
            float wc0 = sW1T[16 * 16 + u], wc1 = sW1T[17 * 16 + u], wc2 = sW1T[18 * 16 + u];
#pragma unroll
            for (int k = 0; k < EPT; k++) {
                float a1 = sB1[u];
#pragma unroll
                for (int m4 = 0; m4 < 4; m4++) {
                    float4 hv = *(const float4*)&sH[1][w][(2 * k + g) * 16 + m4 * 4];
                    a1 = fmaf(hv.x, sW1T[(m4 * 4 + 0) * 16 + u], a1);
                    a1 = fmaf(hv.y, sW1T[(m4 * 4 + 1) * 16 + u], a1);
                    a1 = fmaf(hv.z, sW1T[(m4 * 4 + 2) * 16 + u], a1);
                    a1 = fmaf(hv.w, sW1T[(m4 * 4 + 3) * 16 + u], a1);
                }
                a1 = fmaf(c0[k], wc0, a1);
                a1 = fmaf(c1[k], wc1, a1);
                a1 = fmaf(c2[k], wc2, a1);
                sH[0][w][(2 * k + g) * 16 + u] = tnha(a1);
            }
        }
        __syncwarp();

        // ---- FC2 + FC3; element-sequential ----
        float w3v = sW3[u];
        float* outg = out + ebase + g;
#pragma unroll
        for (int k = 0; k < EPT; k++) {
            float a2 = sB2[u];
#pragma unroll
            for (int m4 = 0; m4 < 4; m4++) {
                float4 xv = *(const float4*)&sH[0][w][(2 * k + g) * 16 + m4 * 4];
                a2 = fmaf(xv.x, sW2T[(m4 * 4 + 0) * 16 + u], a2);
                a2 = fmaf(xv.y, sW2T[(m4 * 4 + 1) * 16 + u], a2);
                a2 = fmaf(xv.z, sW2T[(m4 * 4 + 2) * 16 + u], a2);
                a2 = fmaf(xv.w, sW2T[(m4 * 4 + 3) * 16 + u], a2);
            }
            float p = tnha(a2) * w3v;
#pragma unroll
            for (int off = 8; off; off >>= 1)
                p += __shfl_xor_sync(0xffffffffu, p, off, 16);
            if (u == 0) outg[2 * k] = fmaxf(p + sB3[0], 0.0f);
        }
    }
}

extern "C" void kernel_launch(void* const* d_in, const int* in_sizes, int n_in,
                              void* d_out, int out_size)
{
    const float* mob  = (const float*)d_in[0];
    const float* ctrl = (const float*)d_in[1];
    const float* Wcc  = (const float*)d_in[3];
    const float* bcc  = (const float*)d_in[4];
    const float* Wih  = (const float*)d_in[5];
    const float* Whh  = (const float*)d_in[6];
    const float* bih  = (const float*)d_in[7];
    const float* bhh  = (const float*)d_in[8];
    const float* W1   = (const float*)d_in[9];
    const float* b1   = (const float*)d_in[10];
    const float* W2   = (const float*)d_in[11];
    const float* b2   = (const float*)d_in[12];
    const float* W3   = (const float*)d_in[13];
    const float* b3   = (const float*)d_in[14];

    int B = in_sizes[2];
    int per_block = 2 * EPT * NW * NB;                 // 256 elements per block
    int blocks = (B + per_block - 1) / per_block;      // 4096 for B=1M

    infect_lstm_kernel<<<blocks, 128>>>(mob, ctrl, Wcc, bcc, Wih, Whh, bih, bhh,
                                        W1, b1, W2, b2, W3, b3, (float*)d_out);
}